// round 13
// baseline (speedup 1.0000x reference)
#include <cuda_runtime.h>
#include <cuda_bf16.h>
#include <cstdint>

#define BB 64
#define TT 2048
#define EE 256
#define BT (BB*TT)
#define CHUNK 32
#define NCHUNK (TT/CHUNK)              // 64
#define NSEG 16                        // scan segments (blocks 0..15)
#define SEGLEN 128
#define GATE_BLOCKS 256                // 8 warps each, 2 CTAs/SM
#define TPB 256
#define WPB 8                          // gate warps per block
#define FULLCNT 2048                   // 256 blocks * 8 warps per chunk
#define PFDIST 12                      // L2 prefetch lookahead (chunks)

// xg time-major [T+pad][B] float4 (gates i,f,g,o; sigmoid gates pre-halved, bias folded)
__device__ __align__(16) float4 g_xg[(TT + 16) * BB];
// producer->scan per-chunk counters (reset by last-finishing poller)
__device__ __align__(16) int g_cnt[NCHUNK];
// poller completion rendezvous
__device__ int g_done;

__device__ __forceinline__ float tanha(float x) {
    float y; asm("tanh.approx.f32 %0, %1;" : "=f"(y) : "f"(x)); return y;
}
__device__ __forceinline__ int acq_ld(const int* p) {
    int v; asm volatile("ld.acquire.gpu.global.b32 %0, [%1];" : "=r"(v) : "l"(p) : "memory"); return v;
}
__device__ __forceinline__ void rel_add(int* p, int v) {
    asm volatile("red.release.gpu.global.add.s32 [%0], %1;" :: "l"(p), "r"(v) : "memory");
}
__device__ __forceinline__ int atom_aa(int* p, int v) {
    int o; asm volatile("atom.acq_rel.gpu.global.add.s32 %0, [%1], %2;"
                        : "=r"(o) : "l"(p), "r"(v) : "memory"); return o;
}
__device__ __forceinline__ void pf_l2(const void* p) {
    asm volatile("prefetch.global.L2 [%0];" :: "l"(p));
}
__device__ __forceinline__ float sigf(float h) {
    return fmaf(0.5f, tanha(0.5f * h), 0.5f);
}
// named barriers, 96 participants (3 warps). 1=XRDY, 2/3=HFULL(par), 4/5=HFREE(par)
#define BARS96(id) asm volatile("bar.sync %0, 96;"   :: "r"(id) : "memory")
#define BARA96(id) asm volatile("bar.arrive %0, 96;" :: "r"(id) : "memory")

__global__ __launch_bounds__(TPB, 2) void fused_kernel(
    const float* __restrict__ data,
    const int*   __restrict__ seq,
    const float* __restrict__ w_ih,
    const float* __restrict__ w_hh,
    const float* __restrict__ b_ih,
    const float* __restrict__ b_hh,
    float* __restrict__ out,
    int tail)
{
    const int tid  = threadIdx.x;
    const int warp = tid >> 5;
    const int lane = tid & 31;

    if (blockIdx.x < NSEG) {
        // ========== SCAN BLOCK for segment s: warm-up 128 + real 128 steps ==========
        const int s  = blockIdx.x;
        const int tw = (s == 0) ? 0 : s * SEGLEN - SEGLEN;   // first (warm) step
        const int nchunks = (s == 0) ? 4 : 8;
        const int warmch  = nchunks - 4;
        const int gk0 = tw >> 5;                             // first global chunk

        __shared__ float hbuf[2][BB][33];                    // [parity][chain][step]

        if (warp >= 4) return;

        if (warp == 2) {
            // ---------------- poller warp ----------------
            int ready = 0;
            for (int k = 0; k < nchunks; k++) {
                int need = gk0 + k + 2; if (need > NCHUNK) need = NCHUNK;
                while (ready < need) {
                    int far = ready + 6; if (far > NCHUNK-1) far = NCHUNK-1;
                    if (acq_ld(g_cnt + far) == FULLCNT)        ready = far + 1;
                    else if (acq_ld(g_cnt + ready) == FULLCNT) ready++;
                }
                BARS96(1);                                   // XRDY for chunk k
            }
            __syncwarp();
            if (lane == 0) {
                if (atom_aa(&g_done, 1) == NSEG - 1) {       // last poller: reset
#pragma unroll
                    for (int i = 0; i < NCHUNK; i++) g_cnt[i] = 0;
                    g_done = 0;
                }
            }
            return;
        }

        if (warp == 3) {
            // ---------------- consumer warp: sigmoid + mask + store ----------------
            for (int rc = 0; rc < 4; rc++) {
                const int p = rc & 1;
                BARS96(2 + p);                               // HFULL
                const int tcol = s * SEGLEN + rc * 32 + lane;
#pragma unroll 4
                for (int b = 0; b < BB; b++) {
                    float h = hbuf[p][b][lane];
                    int sq = __ldg(seq + b);
                    float v = (tcol < sq) ? sigf(h) : 0.5f;
                    out[(size_t)b * TT + tcol] = v;
                }
                if (rc < 2) BARA96(4 + p);                   // HFREE
            }
            if (s == 0) {                                    // tuple tail: seq as float
                if (lane      < tail) out[BT + lane]      = (float)__ldg(seq + lane);
                if (lane + 32 < tail) out[BT + lane + 32] = (float)__ldg(seq + lane + 32);
            }
            return;
        }

        // ---------------- scan warps 0,1: chains warp*32 + lane ----------------
        const int b = warp * 32 + lane;
        const float w0h = 0.5f * __ldg(w_hh+0);
        const float w1h = 0.5f * __ldg(w_hh+1);
        const float w2f =        __ldg(w_hh+2);
        const float w3h = 0.5f * __ldg(w_hh+3);

        const float4* xp = g_xg + b;                         // element t at xp[t*BB]

        float4 buf[8];
        float half_c = 0.f, h = 0.f;
        int t = tw;

        for (int k = 0; k < nchunks; k++) {
            BARS96(1);                                       // XRDY: chunks <= gk0+k+1 done
            if (k == 0) {
#pragma unroll
                for (int i = 0; i < 8; i++) buf[i] = __ldcg(xp + (tw + i) * BB);
            }
            const bool real = (k >= warmch);
            const int rc = k - warmch;
            const int p = rc & 1;
            if (real && rc >= 2) BARS96(4 + p);              // HFREE before reuse

#pragma unroll
            for (int u = 0; u < CHUNK; u++) {
                float4 x = buf[u & 7];
                buf[u & 7] = __ldcg(xp + (t + u + 8) * BB);  // padded: in bounds

                float g1 = fmaf(w1h, h, x.y);
                float t1 = tanha(g1);
                float g2 = fmaf(w2f, h, x.z);
                float tg = tanha(g2);
                float g0 = fmaf(w0h, h, x.x);
                float t0 = tanha(g0);
                float g3 = fmaf(w3h, h, x.w);
                float t3 = tanha(g3);

                float r  = fmaf(t1, half_c, half_c);         // f * c_prev
                float qq = fmaf(t0, tg, tg);                 // 2 i g
                float c  = fmaf(0.5f, qq, r);
                half_c   = 0.5f * c;
                float o  = fmaf(0.5f, t3, 0.5f);
                float tc = tanha(c);
                h = o * tc;

                if (real) hbuf[p][b][u] = h;
            }
            t += CHUNK;
            if (real) BARA96(2 + p);                         // HFULL
        }
        return;
    }

    // ================= GATE BLOCKS (NSEG .. NSEG+255), 8 warps each =================
    const int kb = blockIdx.x - NSEG;         // 0..255
    const int s  = kb * WPB + warp;           // 0..2047: task slot within each chunk
    const int bidx = s & 63;
    const int trow = s >> 6;                  // 0..31

    const float4* wv = reinterpret_cast<const float4*>(w_ih);
    float4 wr[8];
#pragma unroll
    for (int g = 0; g < 4; g++) {
        wr[2*g]   = __ldg(wv + g*64 + lane);
        wr[2*g+1] = __ldg(wv + g*64 + 32 + lane);
    }
    const float bb0 = __ldg(b_ih+0) + __ldg(b_hh+0);
    const float bb1 = __ldg(b_ih+1) + __ldg(b_hh+1);
    const float bb2 = __ldg(b_ih+2) + __ldg(b_hh+2);
    const float bb3 = __ldg(b_ih+3) + __ldg(b_hh+3);

    const float4* dpb = reinterpret_cast<const float4*>(data)
                      + ((size_t)bidx * TT + trow) * (EE/4);
    const int cstride = CHUNK * (EE/4);

    // prime the L2 with chunks [4, PFDIST): register ring covers [0,4)
#pragma unroll
    for (int pc = 4; pc < PFDIST; pc++) {
        pf_l2(dpb + pc * cstride + lane);
        pf_l2(dpb + pc * cstride + 32 + lane);
    }

    // depth-4 chunk prefetch pipeline (register ring)
    float4 A0[4], A1[4];
#pragma unroll
    for (int p = 0; p < 4; p++) {
        A0[p] = __ldcs(dpb + p * cstride + lane);
        A1[p] = __ldcs(dpb + p * cstride + 32 + lane);
    }

#pragma unroll 4
    for (int c = 0; c < NCHUNK; c++) {
        const int slot = c & 3;
        float4 d0 = A0[slot], d1 = A1[slot];
        if (c + 4 < NCHUNK) {
            A0[slot] = __ldcs(dpb + (c + 4) * cstride + lane);
            A1[slot] = __ldcs(dpb + (c + 4) * cstride + 32 + lane);
        }
        if (c + PFDIST < NCHUNK) {
            pf_l2(dpb + (c + PFDIST) * cstride + lane);
            pf_l2(dpb + (c + PFDIST) * cstride + 32 + lane);
        }

        float a0, a1, a2, a3;
        {
            float4 w0 = wr[0], w1 = wr[1];
            a0 = d0.x*w0.x; a0 = fmaf(d0.y,w0.y,a0); a0 = fmaf(d0.z,w0.z,a0); a0 = fmaf(d0.w,w0.w,a0);
            a0 = fmaf(d1.x,w1.x,a0); a0 = fmaf(d1.y,w1.y,a0); a0 = fmaf(d1.z,w1.z,a0); a0 = fmaf(d1.w,w1.w,a0);
        }
        {
            float4 w0 = wr[2], w1 = wr[3];
            a1 = d0.x*w0.x; a1 = fmaf(d0.y,w0.y,a1); a1 = fmaf(d0.z,w0.z,a1); a1 = fmaf(d0.w,w0.w,a1);
            a1 = fmaf(d1.x,w1.x,a1); a1 = fmaf(d1.y,w1.y,a1); a1 = fmaf(d1.z,w1.z,a1); a1 = fmaf(d1.w,w1.w,a1);
        }
        {
            float4 w0 = wr[4], w1 = wr[5];
            a2 = d0.x*w0.x; a2 = fmaf(d0.y,w0.y,a2); a2 = fmaf(d0.z,w0.z,a2); a2 = fmaf(d0.w,w0.w,a2);
            a2 = fmaf(d1.x,w1.x,a2); a2 = fmaf(d1.y,w1.y,a2); a2 = fmaf(d1.z,w1.z,a2); a2 = fmaf(d1.w,w1.w,a2);
        }
        {
            float4 w0 = wr[6], w1 = wr[7];
            a3 = d0.x*w0.x; a3 = fmaf(d0.y,w0.y,a3); a3 = fmaf(d0.z,w0.z,a3); a3 = fmaf(d0.w,w0.w,a3);
            a3 = fmaf(d1.x,w1.x,a3); a3 = fmaf(d1.y,w1.y,a3); a3 = fmaf(d1.z,w1.z,a3); a3 = fmaf(d1.w,w1.w,a3);
        }
#pragma unroll
        for (int off = 16; off > 0; off >>= 1) {
            a0 += __shfl_xor_sync(0xffffffffu, a0, off);
            a1 += __shfl_xor_sync(0xffffffffu, a1, off);
            a2 += __shfl_xor_sync(0xffffffffu, a2, off);
            a3 += __shfl_xor_sync(0xffffffffu, a3, off);
        }
        if (lane == 0) {
            const int t = c * CHUNK + trow;
            float4 v;
            v.x = 0.5f * (a0 + bb0);
            v.y = 0.5f * (a1 + bb1);
            v.z =         a2 + bb2;
            v.w = 0.5f * (a3 + bb3);
            g_xg[t * BB + bidx] = v;
        }
        __syncthreads();                       // order all 8 warps' xg stores
        if (tid == 0) rel_add(&g_cnt[c], WPB); // cumulative release (+8 per block)
    }
}

extern "C" void kernel_launch(void* const* d_in, const int* in_sizes, int n_in,
                              void* d_out, int out_size)
{
    const float* data = (const float*)d_in[0];
    const int*   seq  = (const int*)  d_in[1];
    const float* w_ih = (const float*)d_in[2];
    const float* w_hh = (const float*)d_in[3];
    const float* b_ih = (const float*)d_in[4];
    const float* b_hh = (const float*)d_in[5];
    float* out = (float*)d_out;

    int tail = out_size - BT;
    if (tail < 0) tail = 0;
    if (tail > BB) tail = BB;

    fused_kernel<<<NSEG + GATE_BLOCKS, TPB>>>(data, seq, w_ih, w_hh, b_ih, b_hh, out, tail);
}

// round 14
// speedup vs baseline: 1.1553x; 1.1553x over previous
#include <cuda_runtime.h>
#include <cuda_bf16.h>
#include <cstdint>

#define BB 64
#define TT 2048
#define EE 256
#define BT (BB*TT)
#define CHUNK 32
#define NCHUNK (TT/CHUNK)              // 64
#define NPAIR (NCHUNK/2)               // 32 chunk-pairs
#define CSTRIDE 32                     // ints between counters = 128B (own L2 sector)
#define NSEG 16                        // scan segments (blocks 0..15)
#define SEGLEN 128
#define GATE_BLOCKS 128
#define TPB 512
#define FULLCNT 2048                   // 128 blocks * 16 warps per pair
#define PFDIST 12                      // L2 prefetch lookahead (chunks)

// xg time-major [T+pad][B] float4 (gates i,f,g,o; sigmoid gates pre-halved, bias folded)
__device__ __align__(16) float4 g_xg[(TT + 16) * BB];
// producer->scan per-PAIR counters, 128B apart (sector-padded; reset by last poller)
__device__ __align__(128) int g_cnt[NPAIR * CSTRIDE];
// poller completion rendezvous
__device__ int g_done;

__device__ __forceinline__ float tanha(float x) {
    float y; asm("tanh.approx.f32 %0, %1;" : "=f"(y) : "f"(x)); return y;
}
__device__ __forceinline__ int acq_ld(const int* p) {
    int v; asm volatile("ld.acquire.gpu.global.b32 %0, [%1];" : "=r"(v) : "l"(p) : "memory"); return v;
}
__device__ __forceinline__ void rel_add(int* p, int v) {
    asm volatile("red.release.gpu.global.add.s32 [%0], %1;" :: "l"(p), "r"(v) : "memory");
}
__device__ __forceinline__ int atom_aa(int* p, int v) {
    int o; asm volatile("atom.acq_rel.gpu.global.add.s32 %0, [%1], %2;"
                        : "=r"(o) : "l"(p), "r"(v) : "memory"); return o;
}
__device__ __forceinline__ void pf_l2(const void* p) {
    asm volatile("prefetch.global.L2 [%0];" :: "l"(p));
}
__device__ __forceinline__ float sigf(float h) {
    return fmaf(0.5f, tanha(0.5f * h), 0.5f);
}
// named barriers, 96 participants (3 warps). 1=XRDY, 2/3=HFULL(par), 4/5=HFREE(par)
#define BARS96(id) asm volatile("bar.sync %0, 96;"   :: "r"(id) : "memory")
#define BARA96(id) asm volatile("bar.arrive %0, 96;" :: "r"(id) : "memory")

__global__ __launch_bounds__(TPB, 1) void fused_kernel(
    const float* __restrict__ data,
    const int*   __restrict__ seq,
    const float* __restrict__ w_ih,
    const float* __restrict__ w_hh,
    const float* __restrict__ b_ih,
    const float* __restrict__ b_hh,
    float* __restrict__ out,
    int tail)
{
    const int tid  = threadIdx.x;
    const int warp = tid >> 5;
    const int lane = tid & 31;

    if (blockIdx.x < NSEG) {
        // ========== SCAN BLOCK for segment s: warm-up 128 + real 128 steps ==========
        const int s  = blockIdx.x;
        const int tw = (s == 0) ? 0 : s * SEGLEN - SEGLEN;   // first (warm) step
        const int nchunks = (s == 0) ? 4 : 8;
        const int warmch  = nchunks - 4;
        const int gk0 = tw >> 5;                             // first global chunk

        __shared__ float hbuf[2][BB][33];                    // [parity][chain][step]

        if (warp >= 4) return;

        if (warp == 2) {
            // ---------------- poller warp (pair-granular, padded counters) ----------------
            int readyp = 0;                                  // pairs < readyp known done
            for (int k = 0; k < nchunks; k++) {
                int need = gk0 + k + 2; if (need > NCHUNK) need = NCHUNK;
                const int needp = (need + 1) >> 1;           // pairs required
                while (readyp < needp) {
                    int far = readyp + 3; if (far > NPAIR-1) far = NPAIR-1;
                    if (acq_ld(g_cnt + far * CSTRIDE) == FULLCNT)         readyp = far + 1;
                    else if (acq_ld(g_cnt + readyp * CSTRIDE) == FULLCNT) readyp++;
                }
                BARS96(1);                                   // XRDY for chunk k
            }
            __syncwarp();
            if (lane == 0) {
                if (atom_aa(&g_done, 1) == NSEG - 1) {       // last poller: reset
#pragma unroll
                    for (int i = 0; i < NPAIR; i++) g_cnt[i * CSTRIDE] = 0;
                    g_done = 0;
                }
            }
            return;
        }

        if (warp == 3) {
            // ---------------- consumer warp: sigmoid + mask + store ----------------
            for (int rc = 0; rc < 4; rc++) {
                const int p = rc & 1;
                BARS96(2 + p);                               // HFULL
                const int tcol = s * SEGLEN + rc * 32 + lane;
#pragma unroll 4
                for (int b = 0; b < BB; b++) {
                    float h = hbuf[p][b][lane];
                    int sq = __ldg(seq + b);
                    float v = (tcol < sq) ? sigf(h) : 0.5f;
                    out[(size_t)b * TT + tcol] = v;
                }
                if (rc < 2) BARA96(4 + p);                   // HFREE
            }
            if (s == 0) {                                    // tuple tail: seq as float
                if (lane      < tail) out[BT + lane]      = (float)__ldg(seq + lane);
                if (lane + 32 < tail) out[BT + lane + 32] = (float)__ldg(seq + lane + 32);
            }
            return;
        }

        // ---------------- scan warps 0,1: chains warp*32 + lane ----------------
        const int b = warp * 32 + lane;
        const float w0h = 0.5f * __ldg(w_hh+0);
        const float w1h = 0.5f * __ldg(w_hh+1);
        const float w2f =        __ldg(w_hh+2);
        const float w3h = 0.5f * __ldg(w_hh+3);

        const float4* xp = g_xg + b;                         // element t at xp[t*BB]

        float4 buf[8];
        float half_c = 0.f, h = 0.f;
        int t = tw;

        for (int k = 0; k < nchunks; k++) {
            BARS96(1);                                       // XRDY: chunks <= gk0+k+1 done
            if (k == 0) {
#pragma unroll
                for (int i = 0; i < 8; i++) buf[i] = __ldcg(xp + (tw + i) * BB);
            }
            const bool real = (k >= warmch);
            const int rc = k - warmch;
            const int p = rc & 1;
            if (real && rc >= 2) BARS96(4 + p);              // HFREE before reuse

#pragma unroll
            for (int u = 0; u < CHUNK; u++) {
                float4 x = buf[u & 7];
                buf[u & 7] = __ldcg(xp + (t + u + 8) * BB);  // padded: in bounds

                float g1 = fmaf(w1h, h, x.y);
                float t1 = tanha(g1);
                float g2 = fmaf(w2f, h, x.z);
                float tg = tanha(g2);
                float g0 = fmaf(w0h, h, x.x);
                float t0 = tanha(g0);
                float g3 = fmaf(w3h, h, x.w);
                float t3 = tanha(g3);

                float r  = fmaf(t1, half_c, half_c);         // f * c_prev
                float qq = fmaf(t0, tg, tg);                 // 2 i g
                float c  = fmaf(0.5f, qq, r);
                half_c   = 0.5f * c;
                float o  = fmaf(0.5f, t3, 0.5f);
                float tc = tanha(c);
                h = o * tc;

                if (real) hbuf[p][b][u] = h;
            }
            t += CHUNK;
            if (real) BARA96(2 + p);                         // HFULL
        }
        return;
    }

    // ================= GATE BLOCKS (NSEG .. NSEG+127) =================
    const int kb = blockIdx.x - NSEG;         // 0..127
    const int s  = kb * 16 + warp;            // 0..2047: task slot within each chunk
    const int bidx = s & 63;
    const int trow = s >> 6;                  // 0..31

    const float4* wv = reinterpret_cast<const float4*>(w_ih);
    float4 wr[8];
#pragma unroll
    for (int g = 0; g < 4; g++) {
        wr[2*g]   = __ldg(wv + g*64 + lane);
        wr[2*g+1] = __ldg(wv + g*64 + 32 + lane);
    }
    const float bb0 = __ldg(b_ih+0) + __ldg(b_hh+0);
    const float bb1 = __ldg(b_ih+1) + __ldg(b_hh+1);
    const float bb2 = __ldg(b_ih+2) + __ldg(b_hh+2);
    const float bb3 = __ldg(b_ih+3) + __ldg(b_hh+3);

    const float4* dpb = reinterpret_cast<const float4*>(data)
                      + ((size_t)bidx * TT + trow) * (EE/4);
    const int cstride = CHUNK * (EE/4);

    // prime the L2 with chunks [4, PFDIST): register ring covers [0,4)
#pragma unroll
    for (int pc = 4; pc < PFDIST; pc++) {
        pf_l2(dpb + pc * cstride + lane);
        pf_l2(dpb + pc * cstride + 32 + lane);
    }

    // depth-4 chunk prefetch pipeline (register ring)
    float4 A0[4], A1[4];
#pragma unroll
    for (int p = 0; p < 4; p++) {
        A0[p] = __ldcs(dpb + p * cstride + lane);
        A1[p] = __ldcs(dpb + p * cstride + 32 + lane);
    }

#pragma unroll 4
    for (int c = 0; c < NCHUNK; c++) {
        const int slot = c & 3;
        float4 d0 = A0[slot], d1 = A1[slot];
        if (c + 4 < NCHUNK) {
            A0[slot] = __ldcs(dpb + (c + 4) * cstride + lane);
            A1[slot] = __ldcs(dpb + (c + 4) * cstride + 32 + lane);
        }
        if (c + PFDIST < NCHUNK) {
            pf_l2(dpb + (c + PFDIST) * cstride + lane);
            pf_l2(dpb + (c + PFDIST) * cstride + 32 + lane);
        }

        float a0, a1, a2, a3;
        {
            float4 w0 = wr[0], w1 = wr[1];
            a0 = d0.x*w0.x; a0 = fmaf(d0.y,w0.y,a0); a0 = fmaf(d0.z,w0.z,a0); a0 = fmaf(d0.w,w0.w,a0);
            a0 = fmaf(d1.x,w1.x,a0); a0 = fmaf(d1.y,w1.y,a0); a0 = fmaf(d1.z,w1.z,a0); a0 = fmaf(d1.w,w1.w,a0);
        }
        {
            float4 w0 = wr[2], w1 = wr[3];
            a1 = d0.x*w0.x; a1 = fmaf(d0.y,w0.y,a1); a1 = fmaf(d0.z,w0.z,a1); a1 = fmaf(d0.w,w0.w,a1);
            a1 = fmaf(d1.x,w1.x,a1); a1 = fmaf(d1.y,w1.y,a1); a1 = fmaf(d1.z,w1.z,a1); a1 = fmaf(d1.w,w1.w,a1);
        }
        {
            float4 w0 = wr[4], w1 = wr[5];
            a2 = d0.x*w0.x; a2 = fmaf(d0.y,w0.y,a2); a2 = fmaf(d0.z,w0.z,a2); a2 = fmaf(d0.w,w0.w,a2);
            a2 = fmaf(d1.x,w1.x,a2); a2 = fmaf(d1.y,w1.y,a2); a2 = fmaf(d1.z,w1.z,a2); a2 = fmaf(d1.w,w1.w,a2);
        }
        {
            float4 w0 = wr[6], w1 = wr[7];
            a3 = d0.x*w0.x; a3 = fmaf(d0.y,w0.y,a3); a3 = fmaf(d0.z,w0.z,a3); a3 = fmaf(d0.w,w0.w,a3);
            a3 = fmaf(d1.x,w1.x,a3); a3 = fmaf(d1.y,w1.y,a3); a3 = fmaf(d1.z,w1.z,a3); a3 = fmaf(d1.w,w1.w,a3);
        }
#pragma unroll
        for (int off = 16; off > 0; off >>= 1) {
            a0 += __shfl_xor_sync(0xffffffffu, a0, off);
            a1 += __shfl_xor_sync(0xffffffffu, a1, off);
            a2 += __shfl_xor_sync(0xffffffffu, a2, off);
            a3 += __shfl_xor_sync(0xffffffffu, a3, off);
        }
        if (lane == 0) {
            const int t = c * CHUNK + trow;
            float4 v;
            v.x = 0.5f * (a0 + bb0);
            v.y = 0.5f * (a1 + bb1);
            v.z =         a2 + bb2;
            v.w = 0.5f * (a3 + bb3);
            g_xg[t * BB + bidx] = v;
        }
        __syncthreads();                       // orders all 16 warps' stores (both chunks of pair)
        if ((c & 1) && tid == 0)               // one RED per block per PAIR, padded address
            rel_add(&g_cnt[(c >> 1) * CSTRIDE], 16);
    }
}

extern "C" void kernel_launch(void* const* d_in, const int* in_sizes, int n_in,
                              void* d_out, int out_size)
{
    const float* data = (const float*)d_in[0];
    const int*   seq  = (const int*)  d_in[1];
    const float* w_ih = (const float*)d_in[2];
    const float* w_hh = (const float*)d_in[3];
    const float* b_ih = (const float*)d_in[4];
    const float* b_hh = (const float*)d_in[5];
    float* out = (float*)d_out;

    int tail = out_size - BT;
    if (tail < 0) tail = 0;
    if (tail > BB) tail = BB;

    fused_kernel<<<NSEG + GATE_BLOCKS, TPB>>>(data, seq, w_ih, w_hh, b_ih, b_hh, out, tail);
}

// round 15
// speedup vs baseline: 1.2432x; 1.0761x over previous
#include <cuda_runtime.h>
#include <cuda_bf16.h>
#include <cstdint>

#define BB 64
#define TT 2048
#define EE 256
#define BT (BB*TT)
#define CHUNK 32
#define NCHUNK (TT/CHUNK)              // 64
#define NPAIR (NCHUNK/2)               // 32 chunk-pairs
#define CSTRIDE 32                     // ints between counters = 128B (own L2 sector)
#define NSEG 16                        // scan segments (blocks 0..15)
#define SEGLEN 128
#define GATE_BLOCKS 128
#define TPB 512
#define FULLCNT 2048                   // 128 blocks * 16 warps per pair

// xg time-major [T+pad][B] float4 (gates i,f,g,o; sigmoid gates pre-halved, bias folded)
__device__ __align__(16) float4 g_xg[(TT + 16) * BB];
// producer->scan per-PAIR counters, 128B apart (sector-padded; reset by last poller)
__device__ __align__(128) int g_cnt[NPAIR * CSTRIDE];
// poller completion rendezvous
__device__ int g_done;

__device__ __forceinline__ float tanha(float x) {
    float y; asm("tanh.approx.f32 %0, %1;" : "=f"(y) : "f"(x)); return y;
}
__device__ __forceinline__ int acq_ld(const int* p) {
    int v; asm volatile("ld.acquire.gpu.global.b32 %0, [%1];" : "=r"(v) : "l"(p) : "memory"); return v;
}
__device__ __forceinline__ void rel_add(int* p, int v) {
    asm volatile("red.release.gpu.global.add.s32 [%0], %1;" :: "l"(p), "r"(v) : "memory");
}
__device__ __forceinline__ int atom_aa(int* p, int v) {
    int o; asm volatile("atom.acq_rel.gpu.global.add.s32 %0, [%1], %2;"
                        : "=r"(o) : "l"(p), "r"(v) : "memory"); return o;
}
__device__ __forceinline__ float sigf(float h) {
    return fmaf(0.5f, tanha(0.5f * h), 0.5f);
}
// named barriers: 1 = XRDY (160 = 4 scan warps + poller); 2..5 = HFULL slot (96)
#define BXRDY()    asm volatile("bar.sync 1, 160;" ::: "memory")
#define BHFULLA(i) asm volatile("bar.arrive %0, 96;" :: "r"(2 + (i)) : "memory")
#define BHFULLS(i) asm volatile("bar.sync %0, 96;"   :: "r"(2 + (i)) : "memory")

__global__ __launch_bounds__(TPB, 1) void fused_kernel(
    const float* __restrict__ data,
    const int*   __restrict__ seq,
    const float* __restrict__ w_ih,
    const float* __restrict__ w_hh,
    const float* __restrict__ b_ih,
    const float* __restrict__ b_hh,
    float* __restrict__ out,
    int tail)
{
    const int tid  = threadIdx.x;
    const int warp = tid >> 5;
    const int lane = tid & 31;

    if (blockIdx.x < NSEG) {
        // ===== SCAN BLOCK, segment s. Two scan pairs (warps 0-1, 4-5), each
        //       warm-up >=64 + 64 real steps. Poller=warp2, consumer=warp3. =====
        const int s  = blockIdx.x;
        const int gk0 = (s == 0) ? 0 : s * 4 - 4;            // first global chunk
        const int nchunks = (s == 0) ? 4 : 8;

        __shared__ float hbuf[4][BB][33];                    // [real chunk slot][chain][step]

        if (warp >= 6 || warp == 2 || warp == 3) {
            if (warp == 2) {
                // ---------------- poller warp ----------------
                int readyp = 0;
                for (int k = 0; k < nchunks; k++) {
                    int need = gk0 + k + 2; if (need > NCHUNK) need = NCHUNK;
                    const int needp = (need + 1) >> 1;
                    while (readyp < needp) {
                        int far = readyp + 3; if (far > NPAIR-1) far = NPAIR-1;
                        if (acq_ld(g_cnt + far * CSTRIDE) == FULLCNT)         readyp = far + 1;
                        else if (acq_ld(g_cnt + readyp * CSTRIDE) == FULLCNT) readyp++;
                    }
                    BXRDY();
                }
                __syncwarp();
                if (lane == 0) {
                    if (atom_aa(&g_done, 1) == NSEG - 1) {   // last poller: reset
#pragma unroll
                        for (int i = 0; i < NPAIR; i++) g_cnt[i * CSTRIDE] = 0;
                        g_done = 0;
                    }
                }
            } else if (warp == 3) {
                // ---------------- consumer warp: sigmoid + mask + store ----------------
                for (int rc = 0; rc < 4; rc++) {
                    BHFULLS(rc);                             // slot rc full
                    const int tcol = s * SEGLEN + rc * 32 + lane;
#pragma unroll 4
                    for (int b = 0; b < BB; b++) {
                        float h = hbuf[rc][b][lane];
                        int sq = __ldg(seq + b);
                        float v = (tcol < sq) ? sigf(h) : 0.5f;
                        out[(size_t)b * TT + tcol] = v;
                    }
                }
                if (s == 0) {                                // tuple tail: seq as float
                    if (lane      < tail) out[BT + lane]      = (float)__ldg(seq + lane);
                    if (lane + 32 < tail) out[BT + lane + 32] = (float)__ldg(seq + lane + 32);
                }
            }
            return;
        }

        // ---------------- scan pairs: warps {0,1}=pid0, {4,5}=pid1 ----------------
        const int pid = warp >> 2;                           // 0 or 1
        const int b = ((warp & 1) << 5) + lane;              // chain 0..63
        // local-k ranges: pid0 real = first 2 real chunks, pid1 = last 2
        int kstart, realk0, kend;
        if (s == 0) { kstart = 0;           realk0 = (pid == 0) ? 0 : 2; }
        else        { kstart = pid * 2;     realk0 = 4 + pid * 2;        }
        if (s == 0 && pid == 0) kend = 2; else kend = ((s == 0) ? realk0 + 2 : kstart + 6);

        const float w0h = 0.5f * __ldg(w_hh+0);
        const float w1h = 0.5f * __ldg(w_hh+1);
        const float w2f =        __ldg(w_hh+2);
        const float w3h = 0.5f * __ldg(w_hh+3);

        const float4* xp = g_xg + b;                         // element t at xp[t*BB]

        float4 buf[8];
        float half_c = 0.f, h = 0.f;
        int t = (gk0 + kstart) * CHUNK;

        for (int k = 0; k < nchunks; k++) {
            BXRDY();                                         // chunks <= gk0+k+1 ready
            if (k < kstart || k >= kend) continue;
            if (k == kstart) {
#pragma unroll
                for (int i = 0; i < 8; i++) buf[i] = __ldcg(xp + (t + i) * BB);
            }
            const bool real = (k >= realk0);
            const int slot = pid * 2 + (k - realk0);         // 0..3 when real

#pragma unroll
            for (int u = 0; u < CHUNK; u++) {
                float4 x = buf[u & 7];
                buf[u & 7] = __ldcg(xp + (t + u + 8) * BB);  // padded: in bounds

                float g1 = fmaf(w1h, h, x.y);
                float t1 = tanha(g1);
                float g2 = fmaf(w2f, h, x.z);
                float tg = tanha(g2);
                float g0 = fmaf(w0h, h, x.x);
                float t0 = tanha(g0);
                float g3 = fmaf(w3h, h, x.w);
                float t3 = tanha(g3);

                float r  = fmaf(t1, half_c, half_c);         // f * c_prev
                float qq = fmaf(t0, tg, tg);                 // 2 i g
                float c  = fmaf(0.5f, qq, r);
                half_c   = 0.5f * c;
                float o  = fmaf(0.5f, t3, 0.5f);
                float tc = tanha(c);
                h = o * tc;

                if (real) hbuf[slot][b][u] = h;
            }
            t += CHUNK;
            if (real) BHFULLA(slot);                         // slot full
        }
        return;
    }

    // ================= GATE BLOCKS (NSEG .. NSEG+127) =================
    const int kb = blockIdx.x - NSEG;         // 0..127
    const int s  = kb * 16 + warp;            // 0..2047: task slot within each chunk
    const int bidx = s & 63;
    const int trow = s >> 6;                  // 0..31

    const float4* wv = reinterpret_cast<const float4*>(w_ih);
    float4 wr[8];
#pragma unroll
    for (int g = 0; g < 4; g++) {
        wr[2*g]   = __ldg(wv + g*64 + lane);
        wr[2*g+1] = __ldg(wv + g*64 + 32 + lane);
    }
    // per-lane (lanes 0-3) pre-scaled bias: v = fmaf(sc, gatesum, scbb)
    const int   myg   = lane & 3;
    const float sc    = (myg == 2) ? 1.0f : 0.5f;
    const float scbb  = sc * (__ldg(b_ih + myg) + __ldg(b_hh + myg));

    const float4* dpb = reinterpret_cast<const float4*>(data)
                      + ((size_t)bidx * TT + trow) * (EE/4);
    const int cstride = CHUNK * (EE/4);

    // depth-4 chunk prefetch pipeline (register ring)
    float4 A0[4], A1[4];
#pragma unroll
    for (int p = 0; p < 4; p++) {
        A0[p] = __ldcs(dpb + p * cstride + lane);
        A1[p] = __ldcs(dpb + p * cstride + 32 + lane);
    }

#pragma unroll 4
    for (int c = 0; c < NCHUNK; c++) {
        const int slot = c & 3;
        float4 d0 = A0[slot], d1 = A1[slot];
        if (c + 4 < NCHUNK) {
            A0[slot] = __ldcs(dpb + (c + 4) * cstride + lane);
            A1[slot] = __ldcs(dpb + (c + 4) * cstride + 32 + lane);
        }

        float a0, a1, a2, a3;
        {
            float4 w0 = wr[0], w1 = wr[1];
            a0 = d0.x*w0.x; a0 = fmaf(d0.y,w0.y,a0); a0 = fmaf(d0.z,w0.z,a0); a0 = fmaf(d0.w,w0.w,a0);
            a0 = fmaf(d1.x,w1.x,a0); a0 = fmaf(d1.y,w1.y,a0); a0 = fmaf(d1.z,w1.z,a0); a0 = fmaf(d1.w,w1.w,a0);
        }
        {
            float4 w0 = wr[2], w1 = wr[3];
            a1 = d0.x*w0.x; a1 = fmaf(d0.y,w0.y,a1); a1 = fmaf(d0.z,w0.z,a1); a1 = fmaf(d0.w,w0.w,a1);
            a1 = fmaf(d1.x,w1.x,a1); a1 = fmaf(d1.y,w1.y,a1); a1 = fmaf(d1.z,w1.z,a1); a1 = fmaf(d1.w,w1.w,a1);
        }
        {
            float4 w0 = wr[4], w1 = wr[5];
            a2 = d0.x*w0.x; a2 = fmaf(d0.y,w0.y,a2); a2 = fmaf(d0.z,w0.z,a2); a2 = fmaf(d0.w,w0.w,a2);
            a2 = fmaf(d1.x,w1.x,a2); a2 = fmaf(d1.y,w1.y,a2); a2 = fmaf(d1.z,w1.z,a2); a2 = fmaf(d1.w,w1.w,a2);
        }
        {
            float4 w0 = wr[6], w1 = wr[7];
            a3 = d0.x*w0.x; a3 = fmaf(d0.y,w0.y,a3); a3 = fmaf(d0.z,w0.z,a3); a3 = fmaf(d0.w,w0.w,a3);
            a3 = fmaf(d1.x,w1.x,a3); a3 = fmaf(d1.y,w1.y,a3); a3 = fmaf(d1.z,w1.z,a3); a3 = fmaf(d1.w,w1.w,a3);
        }
        // transpose-reduce: 2 exchange rounds -> lane%4 = gate, then 3 butterflies
        const bool o1 = (lane & 1), o2 = ((lane & 2) != 0);
        float s01 = o1 ? a0 : a1;
        float r01 = __shfl_xor_sync(0xffffffffu, s01, 1);
        float b01 = (o1 ? a1 : a0) + r01;
        float s23 = o1 ? a2 : a3;
        float r23 = __shfl_xor_sync(0xffffffffu, s23, 1);
        float b23 = (o1 ? a3 : a2) + r23;
        float sx  = o2 ? b01 : b23;
        float rx  = __shfl_xor_sync(0xffffffffu, sx, 2);
        float cv  = (o2 ? b23 : b01) + rx;
        cv += __shfl_xor_sync(0xffffffffu, cv, 4);
        cv += __shfl_xor_sync(0xffffffffu, cv, 8);
        cv += __shfl_xor_sync(0xffffffffu, cv, 16);

        if (lane < 4) {
            const int t = c * CHUNK + trow;
            reinterpret_cast<float*>(g_xg + t * BB + bidx)[lane] = fmaf(sc, cv, scbb);
        }
        if (c & 1) {
            __syncthreads();                               // order both chunks of the pair
            if (tid == 0) rel_add(&g_cnt[(c >> 1) * CSTRIDE], 16);
        }
    }
}

extern "C" void kernel_launch(void* const* d_in, const int* in_sizes, int n_in,
                              void* d_out, int out_size)
{
    const float* data = (const float*)d_in[0];
    const int*   seq  = (const int*)  d_in[1];
    const float* w_ih = (const float*)d_in[2];
    const float* w_hh = (const float*)d_in[3];
    const float* b_ih = (const float*)d_in[4];
    const float* b_hh = (const float*)d_in[5];
    float* out = (float*)d_out;

    int tail = out_size - BT;
    if (tail < 0) tail = 0;
    if (tail > BB) tail = BB;

    fused_kernel<<<NSEG + GATE_BLOCKS, TPB>>>(data, seq, w_ih, w_hh, b_ih, b_hh, out, tail);
}